// round 14
// baseline (speedup 1.0000x reference)
#include <cuda_runtime.h>

#define NN 131072
#define EE 2097152
#define GB 8
#define CWD 64

// ---------------- static device scratch ----------------
__device__ __align__(16) int d_cnt[NN];
__device__ int d_rowptr[NN + 1];
__device__ int d_cursor[NN];
__device__ int d_csr_src[EE];
__device__ unsigned d_agg[128];          // lookback aggregates (flag in bit31)
__device__ float2 d_acc[NN];             // conv1 edge-parallel accumulator
__device__ float d_hA[NN * CWD];
__device__ float d_hB[NN * CWD];
__device__ float d_xw[NN * CWD];
__device__ float d_score[NN];
__device__ float d_dis[NN];
__device__ int d_c2oA[NN];
__device__ int d_c2oB[NN];
__device__ int d_o2c[NN];
__device__ int d_oldidx[NN];
__device__ unsigned d_romax[4 * GB * CWD];
__device__ float d_rosum[4 * GB * CWD];
__device__ float d_WT[4][CWD * CWD];  // transposed Wl2, Wr2, W4, W5

__device__ __forceinline__ unsigned fkey(float f) {
    unsigned b = __float_as_uint(f);
    return (b & 0x80000000u) ? ~b : (b | 0x80000000u);
}
__device__ __forceinline__ float unfkey(unsigned u) {
    unsigned b = (u & 0x80000000u) ? (u & 0x7fffffffu) : ~u;
    return __uint_as_float(b);
}

__device__ __forceinline__ int wscan_incl(int v, int lane) {
    int incl = v;
    #pragma unroll
    for (int off = 1; off < 32; off <<= 1) {
        int n = __shfl_up_sync(0xffffffffu, incl, off);
        if (lane >= off) incl += n;
    }
    return incl;
}

// ---------------- hist + folded init work ----------------
__global__ void hist_kernel(const int* __restrict__ dst,
                            const float* __restrict__ Wl2, const float* __restrict__ Wr2,
                            const float* __restrict__ W4, const float* __restrict__ W5) {
    int e = blockIdx.x * blockDim.x + threadIdx.x;
    atomicAdd(&d_cnt[dst[e]], 1);
    if (e < NN) d_acc[e] = make_float2(0.f, 0.f);
    if (e < 4 * GB * CWD) { d_romax[e] = 0u; d_rosum[e] = 0.f; }
    if (e < 4 * 4096) {
        int slot = e >> 12;
        int j = e & 4095;
        const float* W = slot == 0 ? Wl2 : slot == 1 ? Wr2 : slot == 2 ? W4 : W5;
        int r = j >> 6, c = j & 63;
        d_WT[slot][c * 64 + r] = W[j];
    }
}

// ---------------- single-kernel scan (decoupled lookback, 128 blocks co-resident) ----------------
__global__ void __launch_bounds__(256, 4) scanfused_kernel() {
    __shared__ int s_warp[8];
    __shared__ int s_off;
    int t = threadIdx.x, b = blockIdx.x;
    int lane = t & 31, w = t >> 5;
    int i0 = b * 1024 + t * 4;
    int4 v = *(const int4*)&d_cnt[i0];
    int s = v.x + v.y + v.z + v.w;
    int incl = wscan_incl(s, lane);
    if (lane == 31) s_warp[w] = incl;
    __syncthreads();
    if (t == 0) {
        int acc = 0;
        #pragma unroll
        for (int ww = 0; ww < 8; ww++) { int tmp = s_warp[ww]; s_warp[ww] = acc; acc += tmp; }
        __threadfence();
        ((volatile unsigned*)d_agg)[b] = (unsigned)acc | 0x80000000u;   // publish aggregate
    } else if (w == 1) {
        int off = 0;
        for (int j = lane; j < b; j += 32) {
            unsigned a;
            do { a = ((volatile unsigned*)d_agg)[j]; } while (!(a >> 31));
            off += (int)(a & 0x7fffffffu);
        }
        for (int o = 16; o; o >>= 1) off += __shfl_xor_sync(0xffffffffu, off, o);
        if (lane == 0) s_off = off;
    }
    __syncthreads();
    int ex = s_off + s_warp[w] + incl - s;
    d_rowptr[i0] = ex;
    d_rowptr[i0 + 1] = ex + v.x;
    d_rowptr[i0 + 2] = ex + v.x + v.y;
    d_rowptr[i0 + 3] = ex + v.x + v.y + v.z;
    d_cursor[i0] = ex;
    d_cursor[i0 + 1] = ex + v.x;
    d_cursor[i0 + 2] = ex + v.x + v.y;
    d_cursor[i0 + 3] = ex + v.x + v.y + v.z;
    *(int4*)&d_cnt[i0] = make_int4(0, 0, 0, 0);   // re-zero for next call
    if (b == 127 && t == 0) d_rowptr[NN] = EE;
}

// ---------------- scatter + fused conv1 edge aggregation ----------------
__global__ void scatter_kernel(const int* __restrict__ src, const int* __restrict__ dst,
                               const float* __restrict__ x) {
    int e = blockIdx.x * blockDim.x + threadIdx.x;
    int s = src[e], d = dst[e];
    int p = atomicAdd(&d_cursor[d], 1);
    d_csr_src[p] = s;
    float2 xv = *(const float2*)&x[2 * s];
    atomicAdd(&d_acc[d].x, xv.x);
    atomicAdd(&d_acc[d].y, xv.y);
    if (e < 128) d_agg[e] = 0;   // reset lookback flags for next call
}

// ---------------- conv1: SAGE (2 -> 64), per-node transform only ----------------
__global__ void conv1_kernel(const float* __restrict__ x,
                             const float* __restrict__ Wl, const float* __restrict__ bl,
                             const float* __restrict__ Wr, const float* __restrict__ wp) {
    int gw = (blockIdx.x * blockDim.x + threadIdx.x) >> 5;
    if (gw >= NN) return;
    int lane = threadIdx.x & 31;
    const float2* x2 = (const float2*)x;
    float deg = (float)(d_rowptr[gw + 1] - d_rowptr[gw]);
    float inv = deg > 0.f ? 1.f / deg : 0.f;
    float2 acc = d_acc[gw];
    float m0 = acc.x * inv, m1 = acc.y * inv;
    float2 xv = x2[gw];
    int d0 = lane, d1 = lane + 32;
    float o0 = Wl[d0 * 2] * m0 + Wl[d0 * 2 + 1] * m1 + bl[d0] + Wr[d0 * 2] * xv.x + Wr[d0 * 2 + 1] * xv.y;
    float o1 = Wl[d1 * 2] * m0 + Wl[d1 * 2 + 1] * m1 + bl[d1] + Wr[d1 * 2] * xv.x + Wr[d1 * 2 + 1] * xv.y;
    o0 = fmaxf(o0, 0.f); o1 = fmaxf(o1, 0.f);
    d_hA[gw * 64 + d0] = o0;
    d_hA[gw * 64 + d1] = o1;
    float w0 = wp[d0], w1 = wp[d1];
    float sd = o0 * w0 + o1 * w1, nw = w0 * w0 + w1 * w1;
    for (int o = 16; o; o >>= 1) {
        sd += __shfl_xor_sync(0xffffffffu, sd, o);
        nw += __shfl_xor_sync(0xffffffffu, nw, o);
    }
    if (lane == 0) d_score[gw] = tanhf(sd * rsqrtf(nw));
}

// ---------------- fused radix select + compact (one block per graph, parallel bin scan) ----------------
__global__ void __launch_bounds__(1024, 1) selcompact_kernel(int m, int k, int flip, int identity) {
    __shared__ unsigned hist[256];
    __shared__ int s_wsum[8];
    __shared__ unsigned s_pref;
    __shared__ int s_rem;
    __shared__ int s_ctr;
    __shared__ int s_eq;
    int b = blockIdx.x, t = threadIdx.x;
    int lane = t & 31;
    int base = b * m;
    if (t == 0) { s_pref = 0u; s_rem = k; }
    __syncthreads();
    for (int p = 3; p >= 0; p--) {
        if (t < 256) hist[t] = 0;
        __syncthreads();
        unsigned pref = s_pref;
        int rem_in = s_rem;
        int hs = (p + 1) * 8;
        for (int i = t; i < m; i += 1024) {
            unsigned u = fkey(d_score[base + i]);
            bool cand = (p == 3) || ((u >> hs) == (pref >> hs));
            if (cand) atomicAdd(&hist[(u >> (p * 8)) & 255], 1u);
        }
        __syncthreads();
        unsigned x = 0, incl = 0;
        if (t < 256) {
            int rt = 255 - t;
            x = hist[rt];
            incl = (unsigned)wscan_incl((int)x, lane);
            if (lane == 31) s_wsum[t >> 5] = (int)incl;
        }
        __syncthreads();
        if (t == 0) {
            int acc = 0;
            #pragma unroll
            for (int ww = 0; ww < 8; ww++) { int tmp = s_wsum[ww]; s_wsum[ww] = acc; acc += tmp; }
        }
        __syncthreads();
        if (t < 256) {
            int rt = 255 - t;
            unsigned g = (unsigned)s_wsum[t >> 5] + incl;
            unsigned above = g - x;
            if ((unsigned)rem_in > above && (unsigned)rem_in <= g) {
                s_pref = pref | ((unsigned)rt << (p * 8));
                s_rem = rem_in - (int)above;
            }
        }
        __syncthreads();
    }
    if (t == 0) { s_ctr = 0; s_eq = 0; }
    __syncthreads();
    unsigned th = s_pref;
    int quota = s_rem;
    const int* oldm = flip ? d_c2oB : d_c2oA;
    int* newm = flip ? d_c2oA : d_c2oB;
    for (int i = t; i < m; i += 1024) {
        int c = base + i;
        unsigned u = fkey(d_score[c]);
        bool keep = u > th;
        if (!keep && u == th) keep = (atomicAdd(&s_eq, 1) < quota);
        int orig = identity ? c : oldm[c];
        unsigned keepers = __ballot_sync(0xffffffffu, keep);
        int cnt = __popc(keepers);
        int base_slot = 0;
        if (lane == 0 && cnt > 0) base_slot = atomicAdd(&s_ctr, cnt);
        base_slot = __shfl_sync(0xffffffffu, base_slot, 0);
        if (keep) {
            int slot = base_slot + __popc(keepers & ((1u << lane) - 1u));
            int nc = b * k + slot;
            newm[nc] = orig;
            d_o2c[orig] = nc;
            d_oldidx[nc] = c;
        } else {
            d_o2c[orig] = -1;
        }
    }
}

// ---------------- pool copy + fused readout partials ----------------
__global__ void __launch_bounds__(256) copyro_kernel(int k, int stage) {
    __shared__ float sv[8][64];
    int gw = (blockIdx.x * blockDim.x + threadIdx.x) >> 5;
    int w = (threadIdx.x >> 5);
    int lane = threadIdx.x & 31;
    int oldc = d_oldidx[gw];
    float v = d_score[oldc];
    float2 h = *(const float2*)&d_hA[oldc * 64 + 2 * lane];
    float v0 = h.x * v, v1 = h.y * v;
    *(float2*)&d_hB[gw * 64 + 2 * lane] = make_float2(v0, v1);
    sv[w][2 * lane] = v0;
    sv[w][2 * lane + 1] = v1;
    __syncthreads();
    int t = threadIdx.x;
    if (t < 64) {
        float mx = sv[0][t], sm = 0.f;
        #pragma unroll
        for (int ww = 0; ww < 8; ww++) {
            float f = sv[ww][t];
            mx = fmaxf(mx, f);
            sm += f;
        }
        int b = (blockIdx.x * 8) / k;
        int off = stage * GB * 64 + b * 64 + t;
        atomicMax(&d_romax[off], fkey(mx));
        atomicAdd(&d_rosum[off], sm);
    }
}

// ---------------- SAGE2 fused: MLP-4 agg + tiled transform ----------------
__global__ void __launch_bounds__(256) sage_fused_kernel(const float* __restrict__ bl,
                                                         const float* __restrict__ wp) {
    __shared__ float sWl[4096];
    __shared__ float sWr[4096];
    __shared__ float sm_m[32][64];
    int t = threadIdx.x;
    for (int i = t; i < 4096; i += 256) {
        sWl[i] = d_WT[0][i];
        sWr[i] = d_WT[1][i];
    }
    int lane = t & 31;
    int w = t >> 5;
    int nblock = blockIdx.x * 32;

    for (int q = 0; q < 4; q++) {
        int n = nblock + w * 4 + q;
        int o = d_c2oB[n];
        int row = d_rowptr[o], end = d_rowptr[o + 1];
        float a0x = 0.f, a0y = 0.f, a1x = 0.f, a1y = 0.f;
        float a2x = 0.f, a2y = 0.f, a3x = 0.f, a3y = 0.f;
        int cnt = 0;
        for (int base = row; base < end; base += 32) {
            int e = base + lane;
            int sc = (e < end) ? d_o2c[d_csr_src[e]] : -1;
            cnt += __popc(__ballot_sync(0xffffffffu, sc >= 0));
            #pragma unroll
            for (int j = 0; j < 32; j += 4) {
                int s0 = __shfl_sync(0xffffffffu, sc, j);
                int s1 = __shfl_sync(0xffffffffu, sc, j + 1);
                int s2 = __shfl_sync(0xffffffffu, sc, j + 2);
                int s3 = __shfl_sync(0xffffffffu, sc, j + 3);
                float2 v0 = (s0 >= 0) ? *(const float2*)&d_hB[s0 * 64 + 2 * lane] : make_float2(0.f, 0.f);
                float2 v1 = (s1 >= 0) ? *(const float2*)&d_hB[s1 * 64 + 2 * lane] : make_float2(0.f, 0.f);
                float2 v2 = (s2 >= 0) ? *(const float2*)&d_hB[s2 * 64 + 2 * lane] : make_float2(0.f, 0.f);
                float2 v3 = (s3 >= 0) ? *(const float2*)&d_hB[s3 * 64 + 2 * lane] : make_float2(0.f, 0.f);
                a0x += v0.x; a0y += v0.y;
                a1x += v1.x; a1y += v1.y;
                a2x += v2.x; a2y += v2.y;
                a3x += v3.x; a3y += v3.y;
            }
        }
        float invc = cnt ? 1.f / (float)cnt : 0.f;
        sm_m[w * 4 + q][2 * lane] = (a0x + a1x + a2x + a3x) * invc;
        sm_m[w * 4 + q][2 * lane + 1] = (a0y + a1y + a2y + a3y) * invc;
    }
    __syncthreads();

    int n0 = nblock + w * 4;
    float mA[4], mB[4], hA[4], hB[4], o0[4], o1[4];
    #pragma unroll
    for (int q = 0; q < 4; q++) {
        int n = n0 + q;
        mA[q] = sm_m[w * 4 + q][lane];
        mB[q] = sm_m[w * 4 + q][lane + 32];
        hA[q] = d_hB[n * 64 + lane];
        hB[q] = d_hB[n * 64 + lane + 32];
        o0[q] = 0.f; o1[q] = 0.f;
    }
    #pragma unroll 4
    for (int j = 0; j < 32; j++) {
        float wl0 = sWl[j * 64 + lane], wl1 = sWl[j * 64 + lane + 32];
        float wr0 = sWr[j * 64 + lane], wr1 = sWr[j * 64 + lane + 32];
        #pragma unroll
        for (int q = 0; q < 4; q++) {
            float mj = __shfl_sync(0xffffffffu, mA[q], j);
            float hj = __shfl_sync(0xffffffffu, hA[q], j);
            o0[q] += wl0 * mj + wr0 * hj;
            o1[q] += wl1 * mj + wr1 * hj;
        }
    }
    #pragma unroll 4
    for (int j = 32; j < 64; j++) {
        float wl0 = sWl[j * 64 + lane], wl1 = sWl[j * 64 + lane + 32];
        float wr0 = sWr[j * 64 + lane], wr1 = sWr[j * 64 + lane + 32];
        #pragma unroll
        for (int q = 0; q < 4; q++) {
            float mj = __shfl_sync(0xffffffffu, mB[q], j - 32);
            float hj = __shfl_sync(0xffffffffu, hB[q], j - 32);
            o0[q] += wl0 * mj + wr0 * hj;
            o1[q] += wl1 * mj + wr1 * hj;
        }
    }
    float b0 = bl[lane], b1 = bl[lane + 32];
    float w0 = wp[lane], w1 = wp[lane + 32];
    float nw = w0 * w0 + w1 * w1;
    for (int o = 16; o; o >>= 1) nw += __shfl_xor_sync(0xffffffffu, nw, o);
    float rn = rsqrtf(nw);
    #pragma unroll
    for (int q = 0; q < 4; q++) {
        int n = n0 + q;
        float r0 = fmaxf(o0[q] + b0, 0.f);
        float r1 = fmaxf(o1[q] + b1, 0.f);
        d_hA[n * 64 + lane] = r0;
        d_hA[n * 64 + lane + 32] = r1;
        float sd = r0 * w0 + r1 * w1;
        for (int o = 16; o; o >>= 1) sd += __shfl_xor_sync(0xffffffffu, sd, o);
        if (lane == 0) d_score[n] = tanhf(sd * rn);
    }
}

// ---------------- GCN xw transform (tiled) + fused degree ----------------
__global__ void __launch_bounds__(256) xwdeg_kernel(int M, int slot, int sel) {
    __shared__ float sW[4096];
    int t = threadIdx.x;
    for (int i = t; i < 4096; i += 256) sW[i] = d_WT[slot][i];
    __syncthreads();
    int lane = t & 31;
    int gw = (blockIdx.x * 8) + (t >> 5);
    int n0 = gw * 4;
    float hA[4], hB[4], o0[4], o1[4];
    #pragma unroll
    for (int q = 0; q < 4; q++) {
        int n = n0 + q;
        hA[q] = d_hB[n * 64 + lane];
        hB[q] = d_hB[n * 64 + lane + 32];
        o0[q] = 0.f; o1[q] = 0.f;
    }
    #pragma unroll 4
    for (int j = 0; j < 32; j++) {
        float w0 = sW[j * 64 + lane], w1 = sW[j * 64 + lane + 32];
        #pragma unroll
        for (int q = 0; q < 4; q++) {
            float hj = __shfl_sync(0xffffffffu, hA[q], j);
            o0[q] += w0 * hj;
            o1[q] += w1 * hj;
        }
    }
    #pragma unroll 4
    for (int j = 32; j < 64; j++) {
        float w0 = sW[j * 64 + lane], w1 = sW[j * 64 + lane + 32];
        #pragma unroll
        for (int q = 0; q < 4; q++) {
            float hj = __shfl_sync(0xffffffffu, hB[q], j - 32);
            o0[q] += w0 * hj;
            o1[q] += w1 * hj;
        }
    }
    const int* c2o = sel ? d_c2oB : d_c2oA;
    #pragma unroll
    for (int q = 0; q < 4; q++) {
        int n = n0 + q;
        d_xw[n * 64 + lane] = o0[q];
        d_xw[n * 64 + lane + 32] = o1[q];
        int o = c2o[n];
        int row = d_rowptr[o], end = d_rowptr[o + 1];
        int cnt = 0;
        for (int base = row; base < end; base += 32) {
            int e = base + lane;
            bool live = false;
            if (e < end) live = (d_o2c[d_csr_src[e]] >= 0);
            cnt += __popc(__ballot_sync(0xffffffffu, live));
        }
        if (lane == 0) d_dis[n] = rsqrtf(1.f + (float)cnt);
    }
}

// ---------------- GCN aggregation + epilogue (MLP-4) ----------------
__global__ void __launch_bounds__(256) gcn_kernel(int M, const float* __restrict__ bias,
                                                  const float* __restrict__ wp, int sel) {
    int gw = (blockIdx.x * blockDim.x + threadIdx.x) >> 5;
    if (gw >= M) return;
    int lane = threadIdx.x & 31;
    const int* c2o = sel ? d_c2oB : d_c2oA;
    int o = c2o[gw];
    float dd = d_dis[gw];
    int row = d_rowptr[o], end = d_rowptr[o + 1];
    float a0x = 0.f, a0y = 0.f, a1x = 0.f, a1y = 0.f;
    float a2x = 0.f, a2y = 0.f, a3x = 0.f, a3y = 0.f;
    for (int base = row; base < end; base += 32) {
        int e = base + lane;
        int sc = -1;
        float ds = 0.f;
        if (e < end) {
            sc = d_o2c[d_csr_src[e]];
            if (sc >= 0) ds = d_dis[sc];
        }
        #pragma unroll
        for (int j = 0; j < 32; j += 4) {
            int s0 = __shfl_sync(0xffffffffu, sc, j);
            int s1 = __shfl_sync(0xffffffffu, sc, j + 1);
            int s2 = __shfl_sync(0xffffffffu, sc, j + 2);
            int s3 = __shfl_sync(0xffffffffu, sc, j + 3);
            float d0 = __shfl_sync(0xffffffffu, ds, j);
            float d1 = __shfl_sync(0xffffffffu, ds, j + 1);
            float d2 = __shfl_sync(0xffffffffu, ds, j + 2);
            float d3 = __shfl_sync(0xffffffffu, ds, j + 3);
            float2 v0 = (s0 >= 0) ? *(const float2*)&d_xw[s0 * 64 + 2 * lane] : make_float2(0.f, 0.f);
            float2 v1 = (s1 >= 0) ? *(const float2*)&d_xw[s1 * 64 + 2 * lane] : make_float2(0.f, 0.f);
            float2 v2 = (s2 >= 0) ? *(const float2*)&d_xw[s2 * 64 + 2 * lane] : make_float2(0.f, 0.f);
            float2 v3 = (s3 >= 0) ? *(const float2*)&d_xw[s3 * 64 + 2 * lane] : make_float2(0.f, 0.f);
            a0x += v0.x * d0; a0y += v0.y * d0;
            a1x += v1.x * d1; a1y += v1.y * d1;
            a2x += v2.x * d2; a2y += v2.y * d2;
            a3x += v3.x * d3; a3y += v3.y * d3;
        }
    }
    float ax = (a0x + a1x + a2x + a3x) * dd;
    float ay = (a0y + a1y + a2y + a3y) * dd;
    float2 self = *(const float2*)&d_xw[gw * 64 + 2 * lane];
    float o0 = ax + self.x * dd * dd + bias[2 * lane];
    float o1 = ay + self.y * dd * dd + bias[2 * lane + 1];
    o0 = fmaxf(o0, 0.f); o1 = fmaxf(o1, 0.f);
    *(float2*)&d_hA[gw * 64 + 2 * lane] = make_float2(o0, o1);
    float w0 = wp[2 * lane], w1 = wp[2 * lane + 1];
    float sd = o0 * w0 + o1 * w1, nw = w0 * w0 + w1 * w1;
    for (int s = 16; s; s >>= 1) {
        sd += __shfl_xor_sync(0xffffffffu, sd, s);
        nw += __shfl_xor_sync(0xffffffffu, nw, s);
    }
    if (lane == 0) d_score[gw] = tanhf(sd * rsqrtf(nw));
}

// ---------------- final MLP + softmax ----------------
__global__ void __launch_bounds__(1024, 1) mlp_kernel(const float* __restrict__ Wa, const float* __restrict__ ba,
                           const float* __restrict__ Wb, const float* __restrict__ bb,
                           const float* __restrict__ Wc, const float* __restrict__ bc,
                           float* __restrict__ out) {
    __shared__ float zs[1024];
    __shared__ float za[1024];
    __shared__ float zb[512];
    __shared__ float zc[2048];
    int t = threadIdx.x;
    {
        int b = t >> 7, d = t & 127;
        const float invk[4] = {1.f / 8192.f, 1.f / 4096.f, 1.f / 2048.f, 1.f / 1024.f};
        float acc = 0.f;
        if (d < 64) {
            #pragma unroll
            for (int st = 0; st < 4; st++)
                acc += unfkey(d_romax[st * GB * 64 + b * 64 + d]);
        } else {
            #pragma unroll
            for (int st = 0; st < 4; st++)
                acc += d_rosum[st * GB * 64 + b * 64 + (d - 64)] * invk[st];
        }
        zs[t] = acc;
    }
    __syncthreads();
    {
        int b = t >> 7, o = t & 127;
        float a = ba[o];
        const float* w = Wa + o * 128;
        const float* z = zs + b * 128;
        for (int j = 0; j < 128; j++) a += w[j] * z[j];
        za[t] = fmaxf(a, 0.f);
    }
    __syncthreads();
    if (t < 512) {
        int b = t >> 6, o = t & 63;
        float a = bb[o];
        for (int j = 0; j < 128; j++) a += Wb[o * 128 + j] * za[b * 128 + j];
        zb[t] = fmaxf(a, 0.f);
    }
    __syncthreads();
    for (int q = t; q < 2048; q += 1024) {
        int b = q >> 8, o = q & 255;
        float a = bc[o];
        for (int j = 0; j < 64; j++) a += Wc[o * 64 + j] * zb[b * 64 + j];
        zc[q] = a;
    }
    __syncthreads();
    int w = t >> 5, lane = t & 31;
    if (w < 8) {
        float mx = -3.4e38f;
        for (int i = lane; i < 256; i += 32) mx = fmaxf(mx, zc[w * 256 + i]);
        for (int o = 16; o; o >>= 1) mx = fmaxf(mx, __shfl_xor_sync(0xffffffffu, mx, o));
        float s = 0.f;
        for (int i = lane; i < 256; i += 32) {
            float e = expf(zc[w * 256 + i] - mx);
            zc[w * 256 + i] = e;
            s += e;
        }
        for (int o = 16; o; o >>= 1) s += __shfl_xor_sync(0xffffffffu, s, o);
        float inv = 1.f / s;
        for (int i = lane; i < 256; i += 32) out[w * 256 + i] = zc[w * 256 + i] * inv;
    }
}

// ---------------- launch ----------------
extern "C" void kernel_launch(void* const* d_in, const int* in_sizes, int n_in,
                              void* d_out, int out_size) {
    const float* x = (const float*)d_in[0];
    const int* ei = (const int*)d_in[1];
    const int* src = ei;
    const int* dst = ei + EE;
    const float* Wl1 = (const float*)d_in[2];
    const float* bl1 = (const float*)d_in[3];
    const float* Wr1 = (const float*)d_in[4];
    const float* Wl2 = (const float*)d_in[5];
    const float* bl2 = (const float*)d_in[6];
    const float* Wr2 = (const float*)d_in[7];
    const float* W4  = (const float*)d_in[8];
    const float* b4  = (const float*)d_in[9];
    const float* W5  = (const float*)d_in[10];
    const float* b5  = (const float*)d_in[11];
    const float* wp1 = (const float*)d_in[12];
    const float* wp2 = (const float*)d_in[13];
    const float* wp4 = (const float*)d_in[14];
    const float* wp5 = (const float*)d_in[15];
    const float* Wa  = (const float*)d_in[16];
    const float* ba  = (const float*)d_in[17];
    const float* Wb  = (const float*)d_in[18];
    const float* bb  = (const float*)d_in[19];
    const float* Wc  = (const float*)d_in[20];
    const float* bc  = (const float*)d_in[21];
    float* out = (float*)d_out;

    // CSR build + conv1 aggregation folded into scatter
    hist_kernel<<<EE / 256, 256>>>(dst, Wl2, Wr2, W4, W5);
    scanfused_kernel<<<128, 256>>>();
    scatter_kernel<<<EE / 256, 256>>>(src, dst, x);

    // stage 1: SAGE1 transform on all N nodes, pool 16384 -> 8192
    conv1_kernel<<<NN / 8, 256>>>(x, Wl1, bl1, Wr1, wp1);
    selcompact_kernel<<<GB, 1024>>>(16384, 8192, 0, 1);
    copyro_kernel<<<(GB * 8192) / 8, 256>>>(8192, 0);

    // stage 2: SAGE2 on 65536 nodes (fused agg+transform), pool 8192 -> 4096
    sage_fused_kernel<<<65536 / 32, 256>>>(bl2, wp2);
    selcompact_kernel<<<GB, 1024>>>(8192, 4096, 1, 0);
    copyro_kernel<<<(GB * 4096) / 8, 256>>>(4096, 1);

    // stage 3: GCN on 32768 nodes, pool 4096 -> 2048
    xwdeg_kernel<<<32768 / 32, 256>>>(32768, 2, 0);
    gcn_kernel<<<32768 / 8, 256>>>(32768, b4, wp4, 0);
    selcompact_kernel<<<GB, 1024>>>(4096, 2048, 0, 0);
    copyro_kernel<<<(GB * 2048) / 8, 256>>>(2048, 2);

    // stage 4: GCN on 16384 nodes, pool 2048 -> 1024
    xwdeg_kernel<<<16384 / 32, 256>>>(16384, 3, 1);
    gcn_kernel<<<16384 / 8, 256>>>(16384, b5, wp5, 1);
    selcompact_kernel<<<GB, 1024>>>(2048, 1024, 1, 0);
    copyro_kernel<<<(GB * 1024) / 8, 256>>>(1024, 3);

    // final MLP + softmax
    mlp_kernel<<<1, 1024>>>(Wa, ba, Wb, bb, Wc, bc, out);
}

// round 16
// speedup vs baseline: 1.0654x; 1.0654x over previous
#include <cuda_runtime.h>

#define NN 131072
#define EE 2097152
#define GB 8
#define CWD 64
#define EMAX 64

// ---------------- static device scratch ----------------
__device__ __align__(16) int d_cnt[NN];
__device__ int d_rowptr[NN + 1];
__device__ int d_cursor[NN];
__device__ int d_csr_src[EE];
__device__ unsigned d_agg[128];          // lookback aggregates (flag in bit31)
__device__ float d_hA[NN * CWD];
__device__ float d_hB[NN * CWD];
__device__ float d_xw[NN * CWD];
__device__ float d_score[NN];
__device__ float d_dis[NN];
__device__ int d_c2oA[NN];
__device__ int d_c2oB[NN];
__device__ int d_o2c[NN];
__device__ int d_oldidx[NN];
__device__ int d_nedge[NN];              // live-edge count per current node
__device__ int d_elist[NN * EMAX];       // live relabeled neighbor indices
__device__ unsigned d_romax[4 * GB * CWD];
__device__ float d_rosum[4 * GB * CWD];
__device__ float d_WT[4][CWD * CWD];  // transposed Wl2, Wr2, W4, W5

__device__ __forceinline__ unsigned fkey(float f) {
    unsigned b = __float_as_uint(f);
    return (b & 0x80000000u) ? ~b : (b | 0x80000000u);
}
__device__ __forceinline__ float unfkey(unsigned u) {
    unsigned b = (u & 0x80000000u) ? (u & 0x7fffffffu) : ~u;
    return __uint_as_float(b);
}

__device__ __forceinline__ int wscan_incl(int v, int lane) {
    int incl = v;
    #pragma unroll
    for (int off = 1; off < 32; off <<= 1) {
        int n = __shfl_up_sync(0xffffffffu, incl, off);
        if (lane >= off) incl += n;
    }
    return incl;
}

// ---------------- hist + folded init work ----------------
__global__ void hist_kernel(const int* __restrict__ dst,
                            const float* __restrict__ Wl2, const float* __restrict__ Wr2,
                            const float* __restrict__ W4, const float* __restrict__ W5) {
    int e = blockIdx.x * blockDim.x + threadIdx.x;
    atomicAdd(&d_cnt[dst[e]], 1);
    if (e < 4 * GB * CWD) { d_romax[e] = 0u; d_rosum[e] = 0.f; }
    if (e < 4 * 4096) {
        int slot = e >> 12;
        int j = e & 4095;
        const float* W = slot == 0 ? Wl2 : slot == 1 ? Wr2 : slot == 2 ? W4 : W5;
        int r = j >> 6, c = j & 63;
        d_WT[slot][c * 64 + r] = W[j];
    }
}

// ---------------- single-kernel scan (decoupled lookback, 128 blocks co-resident) ----------------
__global__ void __launch_bounds__(256, 4) scanfused_kernel() {
    __shared__ int s_warp[8];
    __shared__ int s_off;
    int t = threadIdx.x, b = blockIdx.x;
    int lane = t & 31, w = t >> 5;
    int i0 = b * 1024 + t * 4;
    int4 v = *(const int4*)&d_cnt[i0];
    int s = v.x + v.y + v.z + v.w;
    int incl = wscan_incl(s, lane);
    if (lane == 31) s_warp[w] = incl;
    __syncthreads();
    if (t == 0) {
        int acc = 0;
        #pragma unroll
        for (int ww = 0; ww < 8; ww++) { int tmp = s_warp[ww]; s_warp[ww] = acc; acc += tmp; }
        __threadfence();
        ((volatile unsigned*)d_agg)[b] = (unsigned)acc | 0x80000000u;   // publish aggregate
    } else if (w == 1) {
        int off = 0;
        for (int j = lane; j < b; j += 32) {
            unsigned a;
            do { a = ((volatile unsigned*)d_agg)[j]; } while (!(a >> 31));
            off += (int)(a & 0x7fffffffu);
        }
        for (int o = 16; o; o >>= 1) off += __shfl_xor_sync(0xffffffffu, off, o);
        if (lane == 0) s_off = off;
    }
    __syncthreads();
    int ex = s_off + s_warp[w] + incl - s;
    d_rowptr[i0] = ex;
    d_rowptr[i0 + 1] = ex + v.x;
    d_rowptr[i0 + 2] = ex + v.x + v.y;
    d_rowptr[i0 + 3] = ex + v.x + v.y + v.z;
    d_cursor[i0] = ex;
    d_cursor[i0 + 1] = ex + v.x;
    d_cursor[i0 + 2] = ex + v.x + v.y;
    d_cursor[i0 + 3] = ex + v.x + v.y + v.z;
    *(int4*)&d_cnt[i0] = make_int4(0, 0, 0, 0);   // re-zero for next call
    if (b == 127 && t == 0) d_rowptr[NN] = EE;
}

__global__ void scatter_kernel(const int* __restrict__ src, const int* __restrict__ dst) {
    int e = blockIdx.x * blockDim.x + threadIdx.x;
    int p = atomicAdd(&d_cursor[dst[e]], 1);
    d_csr_src[p] = src[e];
    if (e < 128) d_agg[e] = 0;   // reset lookback flags for next call
}

// ---------------- conv1: SAGE (2 -> 64), warp per node (full CSR gather) ----------------
__global__ void conv1_kernel(const float* __restrict__ x,
                             const float* __restrict__ Wl, const float* __restrict__ bl,
                             const float* __restrict__ Wr, const float* __restrict__ wp) {
    int gw = (blockIdx.x * blockDim.x + threadIdx.x) >> 5;
    if (gw >= NN) return;
    int lane = threadIdx.x & 31;
    const float2* x2 = (const float2*)x;
    int row = d_rowptr[gw], end = d_rowptr[gw + 1];
    float a0 = 0.f, a1 = 0.f;
    for (int e = row + lane; e < end; e += 32) {
        float2 v = x2[d_csr_src[e]];
        a0 += v.x;
        a1 += v.y;
    }
    for (int o = 16; o; o >>= 1) {
        a0 += __shfl_xor_sync(0xffffffffu, a0, o);
        a1 += __shfl_xor_sync(0xffffffffu, a1, o);
    }
    float deg = (float)(end - row);
    float inv = deg > 0.f ? 1.f / deg : 0.f;
    float m0 = a0 * inv, m1 = a1 * inv;
    float2 xv = x2[gw];
    int d0 = lane, d1 = lane + 32;
    float o0 = Wl[d0 * 2] * m0 + Wl[d0 * 2 + 1] * m1 + bl[d0] + Wr[d0 * 2] * xv.x + Wr[d0 * 2 + 1] * xv.y;
    float o1 = Wl[d1 * 2] * m0 + Wl[d1 * 2 + 1] * m1 + bl[d1] + Wr[d1 * 2] * xv.x + Wr[d1 * 2 + 1] * xv.y;
    o0 = fmaxf(o0, 0.f); o1 = fmaxf(o1, 0.f);
    d_hA[gw * 64 + d0] = o0;
    d_hA[gw * 64 + d1] = o1;
    float w0 = wp[d0], w1 = wp[d1];
    float sd = o0 * w0 + o1 * w1, nw = w0 * w0 + w1 * w1;
    for (int o = 16; o; o >>= 1) {
        sd += __shfl_xor_sync(0xffffffffu, sd, o);
        nw += __shfl_xor_sync(0xffffffffu, nw, o);
    }
    if (lane == 0) d_score[gw] = tanhf(sd * rsqrtf(nw));
}

// ---------------- fused radix select + compact (one block per graph, parallel bin scan) ----------------
__global__ void __launch_bounds__(1024, 1) selcompact_kernel(int m, int k, int flip, int identity) {
    __shared__ unsigned hist[256];
    __shared__ int s_wsum[8];
    __shared__ unsigned s_pref;
    __shared__ int s_rem;
    __shared__ int s_ctr;
    __shared__ int s_eq;
    int b = blockIdx.x, t = threadIdx.x;
    int lane = t & 31;
    int base = b * m;
    if (t == 0) { s_pref = 0u; s_rem = k; }
    __syncthreads();
    for (int p = 3; p >= 0; p--) {
        if (t < 256) hist[t] = 0;
        __syncthreads();
        unsigned pref = s_pref;
        int rem_in = s_rem;
        int hs = (p + 1) * 8;
        for (int i = t; i < m; i += 1024) {
            unsigned u = fkey(d_score[base + i]);
            bool cand = (p == 3) || ((u >> hs) == (pref >> hs));
            if (cand) atomicAdd(&hist[(u >> (p * 8)) & 255], 1u);
        }
        __syncthreads();
        unsigned x = 0, incl = 0;
        if (t < 256) {
            int rt = 255 - t;
            x = hist[rt];
            incl = (unsigned)wscan_incl((int)x, lane);
            if (lane == 31) s_wsum[t >> 5] = (int)incl;
        }
        __syncthreads();
        if (t == 0) {
            int acc = 0;
            #pragma unroll
            for (int ww = 0; ww < 8; ww++) { int tmp = s_wsum[ww]; s_wsum[ww] = acc; acc += tmp; }
        }
        __syncthreads();
        if (t < 256) {
            int rt = 255 - t;
            unsigned g = (unsigned)s_wsum[t >> 5] + incl;
            unsigned above = g - x;
            if ((unsigned)rem_in > above && (unsigned)rem_in <= g) {
                s_pref = pref | ((unsigned)rt << (p * 8));
                s_rem = rem_in - (int)above;
            }
        }
        __syncthreads();
    }
    if (t == 0) { s_ctr = 0; s_eq = 0; }
    __syncthreads();
    unsigned th = s_pref;
    int quota = s_rem;
    const int* oldm = flip ? d_c2oB : d_c2oA;
    int* newm = flip ? d_c2oA : d_c2oB;
    for (int i = t; i < m; i += 1024) {
        int c = base + i;
        unsigned u = fkey(d_score[c]);
        bool keep = u > th;
        if (!keep && u == th) keep = (atomicAdd(&s_eq, 1) < quota);
        int orig = identity ? c : oldm[c];
        unsigned keepers = __ballot_sync(0xffffffffu, keep);
        int cnt = __popc(keepers);
        int base_slot = 0;
        if (lane == 0 && cnt > 0) base_slot = atomicAdd(&s_ctr, cnt);
        base_slot = __shfl_sync(0xffffffffu, base_slot, 0);
        if (keep) {
            int slot = base_slot + __popc(keepers & ((1u << lane) - 1u));
            int nc = b * k + slot;
            newm[nc] = orig;
            d_o2c[orig] = nc;
            d_oldidx[nc] = c;
        } else {
            d_o2c[orig] = -1;
        }
    }
}

// ---------------- pool copy + readout partials + live-edge list build ----------------
__global__ void __launch_bounds__(256) copyro_kernel(int k, int stage, int sel, int build) {
    __shared__ float sv[8][64];
    int gw = (blockIdx.x * blockDim.x + threadIdx.x) >> 5;
    int w = (threadIdx.x >> 5);
    int lane = threadIdx.x & 31;
    int oldc = d_oldidx[gw];
    float v = d_score[oldc];
    float2 h = *(const float2*)&d_hA[oldc * 64 + 2 * lane];
    float v0 = h.x * v, v1 = h.y * v;
    *(float2*)&d_hB[gw * 64 + 2 * lane] = make_float2(v0, v1);
    sv[w][2 * lane] = v0;
    sv[w][2 * lane + 1] = v1;

    if (build) {
        // build compacted live-edge list for node gw
        const int* c2o = sel ? d_c2oB : d_c2oA;
        int o = c2o[gw];
        int row = d_rowptr[o], end = d_rowptr[o + 1];
        int cnt = 0;
        for (int base = row; base < end; base += 32) {
            int e = base + lane;
            int sc = (e < end) ? d_o2c[d_csr_src[e]] : -1;
            unsigned liveb = __ballot_sync(0xffffffffu, sc >= 0);
            int pos = cnt + __popc(liveb & ((1u << lane) - 1u));
            if (sc >= 0 && pos < EMAX) d_elist[gw * EMAX + pos] = sc;
            cnt += __popc(liveb);
        }
        if (lane == 0) {
            d_nedge[gw] = min(cnt, EMAX);
            d_dis[gw] = rsqrtf(1.f + (float)cnt);
        }
    }

    __syncthreads();
    int t = threadIdx.x;
    if (t < 64) {
        float mx = sv[0][t], sm = 0.f;
        #pragma unroll
        for (int ww = 0; ww < 8; ww++) {
            float f = sv[ww][t];
            mx = fmaxf(mx, f);
            sm += f;
        }
        int b = (blockIdx.x * 8) / k;
        int off = stage * GB * 64 + b * 64 + t;
        atomicMax(&d_romax[off], fkey(mx));
        atomicAdd(&d_rosum[off], sm);
    }
}

// ---------------- SAGE2 fused: live-edge MLP-4 agg + tiled transform ----------------
__global__ void __launch_bounds__(256) sage_fused_kernel(const float* __restrict__ bl,
                                                         const float* __restrict__ wp) {
    __shared__ float sWl[4096];
    __shared__ float sWr[4096];
    __shared__ float sm_m[32][64];
    int t = threadIdx.x;
    for (int i = t; i < 4096; i += 256) {
        sWl[i] = d_WT[0][i];
        sWr[i] = d_WT[1][i];
    }
    int lane = t & 31;
    int w = t >> 5;
    int nblock = blockIdx.x * 32;

    for (int q = 0; q < 4; q++) {
        int n = nblock + w * 4 + q;
        int cnt = d_nedge[n];
        float a0x = 0.f, a0y = 0.f, a1x = 0.f, a1y = 0.f;
        float a2x = 0.f, a2y = 0.f, a3x = 0.f, a3y = 0.f;
        for (int base = 0; base < cnt; base += 32) {
            int e = base + lane;
            int sc = (e < cnt) ? d_elist[n * EMAX + e] : -1;
            int nb = min(32, cnt - base);
            for (int j = 0; j < nb; j += 4) {
                int s0 = __shfl_sync(0xffffffffu, sc, j);
                int s1 = __shfl_sync(0xffffffffu, sc, j + 1);
                int s2 = __shfl_sync(0xffffffffu, sc, j + 2);
                int s3 = __shfl_sync(0xffffffffu, sc, j + 3);
                float2 v0 = (s0 >= 0) ? *(const float2*)&d_hB[s0 * 64 + 2 * lane] : make_float2(0.f, 0.f);
                float2 v1 = (s1 >= 0) ? *(const float2*)&d_hB[s1 * 64 + 2 * lane] : make_float2(0.f, 0.f);
                float2 v2 = (s2 >= 0) ? *(const float2*)&d_hB[s2 * 64 + 2 * lane] : make_float2(0.f, 0.f);
                float2 v3 = (s3 >= 0) ? *(const float2*)&d_hB[s3 * 64 + 2 * lane] : make_float2(0.f, 0.f);
                a0x += v0.x; a0y += v0.y;
                a1x += v1.x; a1y += v1.y;
                a2x += v2.x; a2y += v2.y;
                a3x += v3.x; a3y += v3.y;
            }
        }
        float invc = cnt ? 1.f / (float)cnt : 0.f;
        sm_m[w * 4 + q][2 * lane] = (a0x + a1x + a2x + a3x) * invc;
        sm_m[w * 4 + q][2 * lane + 1] = (a0y + a1y + a2y + a3y) * invc;
    }
    __syncthreads();

    int n0 = nblock + w * 4;
    float mA[4], mB[4], hA[4], hB[4], o0[4], o1[4];
    #pragma unroll
    for (int q = 0; q < 4; q++) {
        int n = n0 + q;
        mA[q] = sm_m[w * 4 + q][lane];
        mB[q] = sm_m[w * 4 + q][lane + 32];
        hA[q] = d_hB[n * 64 + lane];
        hB[q] = d_hB[n * 64 + lane + 32];
        o0[q] = 0.f; o1[q] = 0.f;
    }
    #pragma unroll 4
    for (int j = 0; j < 32; j++) {
        float wl0 = sWl[j * 64 + lane], wl1 = sWl[j * 64 + lane + 32];
        float wr0 = sWr[j * 64 + lane], wr1 = sWr[j * 64 + lane + 32];
        #pragma unroll
        for (int q = 0; q < 4; q++) {
            float mj = __shfl_sync(0xffffffffu, mA[q], j);
            float hj = __shfl_sync(0xffffffffu, hA[q], j);
            o0[q] += wl0 * mj + wr0 * hj;
            o1[q] += wl1 * mj + wr1 * hj;
        }
    }
    #pragma unroll 4
    for (int j = 32; j < 64; j++) {
        float wl0 = sWl[j * 64 + lane], wl1 = sWl[j * 64 + lane + 32];
        float wr0 = sWr[j * 64 + lane], wr1 = sWr[j * 64 + lane + 32];
        #pragma unroll
        for (int q = 0; q < 4; q++) {
            float mj = __shfl_sync(0xffffffffu, mB[q], j - 32);
            float hj = __shfl_sync(0xffffffffu, hB[q], j - 32);
            o0[q] += wl0 * mj + wr0 * hj;
            o1[q] += wl1 * mj + wr1 * hj;
        }
    }
    float b0 = bl[lane], b1 = bl[lane + 32];
    float w0 = wp[lane], w1 = wp[lane + 32];
    float nw = w0 * w0 + w1 * w1;
    for (int o = 16; o; o >>= 1) nw += __shfl_xor_sync(0xffffffffu, nw, o);
    float rn = rsqrtf(nw);
    #pragma unroll
    for (int q = 0; q < 4; q++) {
        int n = n0 + q;
        float r0 = fmaxf(o0[q] + b0, 0.f);
        float r1 = fmaxf(o1[q] + b1, 0.f);
        d_hA[n * 64 + lane] = r0;
        d_hA[n * 64 + lane + 32] = r1;
        float sd = r0 * w0 + r1 * w1;
        for (int o = 16; o; o >>= 1) sd += __shfl_xor_sync(0xffffffffu, sd, o);
        if (lane == 0) d_score[n] = tanhf(sd * rn);
    }
}

// ---------------- GCN xw transform (tiled, pure) ----------------
__global__ void __launch_bounds__(256) xw_kernel(int M, int slot) {
    __shared__ float sW[4096];
    int t = threadIdx.x;
    for (int i = t; i < 4096; i += 256) sW[i] = d_WT[slot][i];
    __syncthreads();
    int lane = t & 31;
    int gw = (blockIdx.x * 8) + (t >> 5);
    int n0 = gw * 4;
    float hA[4], hB[4], o0[4], o1[4];
    #pragma unroll
    for (int q = 0; q < 4; q++) {
        int n = n0 + q;
        hA[q] = d_hB[n * 64 + lane];
        hB[q] = d_hB[n * 64 + lane + 32];
        o0[q] = 0.f; o1[q] = 0.f;
    }
    #pragma unroll 4
    for (int j = 0; j < 32; j++) {
        float w0 = sW[j * 64 + lane], w1 = sW[j * 64 + lane + 32];
        #pragma unroll
        for (int q = 0; q < 4; q++) {
            float hj = __shfl_sync(0xffffffffu, hA[q], j);
            o0[q] += w0 * hj;
            o1[q] += w1 * hj;
        }
    }
    #pragma unroll 4
    for (int j = 32; j < 64; j++) {
        float w0 = sW[j * 64 + lane], w1 = sW[j * 64 + lane + 32];
        #pragma unroll
        for (int q = 0; q < 4; q++) {
            float hj = __shfl_sync(0xffffffffu, hB[q], j - 32);
            o0[q] += w0 * hj;
            o1[q] += w1 * hj;
        }
    }
    #pragma unroll
    for (int q = 0; q < 4; q++) {
        int n = n0 + q;
        d_xw[n * 64 + lane] = o0[q];
        d_xw[n * 64 + lane + 32] = o1[q];
    }
}

// ---------------- GCN aggregation + epilogue (live-edge MLP-4) ----------------
__global__ void __launch_bounds__(256) gcn_kernel(int M, const float* __restrict__ bias,
                                                  const float* __restrict__ wp) {
    int gw = (blockIdx.x * blockDim.x + threadIdx.x) >> 5;
    if (gw >= M) return;
    int lane = threadIdx.x & 31;
    float dd = d_dis[gw];
    int cnt = d_nedge[gw];
    float a0x = 0.f, a0y = 0.f, a1x = 0.f, a1y = 0.f;
    float a2x = 0.f, a2y = 0.f, a3x = 0.f, a3y = 0.f;
    for (int base = 0; base < cnt; base += 32) {
        int e = base + lane;
        int sc = (e < cnt) ? d_elist[gw * EMAX + e] : -1;
        int nb = min(32, cnt - base);
        for (int j = 0; j < nb; j += 4) {
            int s0 = __shfl_sync(0xffffffffu, sc, j);
            int s1 = __shfl_sync(0xffffffffu, sc, j + 1);
            int s2 = __shfl_sync(0xffffffffu, sc, j + 2);
            int s3 = __shfl_sync(0xffffffffu, sc, j + 3);
            float d0 = (s0 >= 0) ? d_dis[s0] : 0.f;
            float d1 = (s1 >= 0) ? d_dis[s1] : 0.f;
            float d2 = (s2 >= 0) ? d_dis[s2] : 0.f;
            float d3 = (s3 >= 0) ? d_dis[s3] : 0.f;
            float2 v0 = (s0 >= 0) ? *(const float2*)&d_xw[s0 * 64 + 2 * lane] : make_float2(0.f, 0.f);
            float2 v1 = (s1 >= 0) ? *(const float2*)&d_xw[s1 * 64 + 2 * lane] : make_float2(0.f, 0.f);
            float2 v2 = (s2 >= 0) ? *(const float2*)&d_xw[s2 * 64 + 2 * lane] : make_float2(0.f, 0.f);
            float2 v3 = (s3 >= 0) ? *(const float2*)&d_xw[s3 * 64 + 2 * lane] : make_float2(0.f, 0.f);
            a0x += v0.x * d0; a0y += v0.y * d0;
            a1x += v1.x * d1; a1y += v1.y * d1;
            a2x += v2.x * d2; a2y += v2.y * d2;
            a3x += v3.x * d3; a3y += v3.y * d3;
        }
    }
    float ax = (a0x + a1x + a2x + a3x) * dd;
    float ay = (a0y + a1y + a2y + a3y) * dd;
    float2 self = *(const float2*)&d_xw[gw * 64 + 2 * lane];
    float o0 = ax + self.x * dd * dd + bias[2 * lane];
    float o1 = ay + self.y * dd * dd + bias[2 * lane + 1];
    o0 = fmaxf(o0, 0.f); o1 = fmaxf(o1, 0.f);
    *(float2*)&d_hA[gw * 64 + 2 * lane] = make_float2(o0, o1);
    float w0 = wp[2 * lane], w1 = wp[2 * lane + 1];
    float sd = o0 * w0 + o1 * w1, nw = w0 * w0 + w1 * w1;
    for (int s = 16; s; s >>= 1) {
        sd += __shfl_xor_sync(0xffffffffu, sd, s);
        nw += __shfl_xor_sync(0xffffffffu, nw, s);
    }
    if (lane == 0) d_score[gw] = tanhf(sd * rsqrtf(nw));
}

// ---------------- final MLP + softmax ----------------
__global__ void __launch_bounds__(1024, 1) mlp_kernel(const float* __restrict__ Wa, const float* __restrict__ ba,
                           const float* __restrict__ Wb, const float* __restrict__ bb,
                           const float* __restrict__ Wc, const float* __restrict__ bc,
                           float* __restrict__ out) {
    __shared__ float zs[1024];
    __shared__ float za[1024];
    __shared__ float zb[512];
    __shared__ float zc[2048];
    int t = threadIdx.x;
    {
        int b = t >> 7, d = t & 127;
        const float invk[4] = {1.f / 8192.f, 1.f / 4096.f, 1.f / 2048.f, 1.f / 1024.f};
        float acc = 0.f;
        if (d < 64) {
            #pragma unroll
            for (int st = 0; st < 4; st++)
                acc += unfkey(d_romax[st * GB * 64 + b * 64 + d]);
        } else {
            #pragma unroll
            for (int st = 0; st < 4; st++)
                acc += d_rosum[st * GB * 64 + b * 64 + (d - 64)] * invk[st];
        }
        zs[t] = acc;
    }
    __syncthreads();
    {
        int b = t >> 7, o = t & 127;
        float a = ba[o];
        const float* w = Wa + o * 128;
        const float* z = zs + b * 128;
        for (int j = 0; j < 128; j++) a += w[j] * z[j];
        za[t] = fmaxf(a, 0.f);
    }
    __syncthreads();
    if (t < 512) {
        int b = t >> 6, o = t & 63;
        float a = bb[o];
        for (int j = 0; j < 128; j++) a += Wb[o * 128 + j] * za[b * 128 + j];
        zb[t] = fmaxf(a, 0.f);
    }
    __syncthreads();
    for (int q = t; q < 2048; q += 1024) {
        int b = q >> 8, o = q & 255;
        float a = bc[o];
        for (int j = 0; j < 64; j++) a += Wc[o * 64 + j] * zb[b * 64 + j];
        zc[q] = a;
    }
    __syncthreads();
    int w = t >> 5, lane = t & 31;
    if (w < 8) {
        float mx = -3.4e38f;
        for (int i = lane; i < 256; i += 32) mx = fmaxf(mx, zc[w * 256 + i]);
        for (int o = 16; o; o >>= 1) mx = fmaxf(mx, __shfl_xor_sync(0xffffffffu, mx, o));
        float s = 0.f;
        for (int i = lane; i < 256; i += 32) {
            float e = expf(zc[w * 256 + i] - mx);
            zc[w * 256 + i] = e;
            s += e;
        }
        for (int o = 16; o; o >>= 1) s += __shfl_xor_sync(0xffffffffu, s, o);
        float inv = 1.f / s;
        for (int i = lane; i < 256; i += 32) out[w * 256 + i] = zc[w * 256 + i] * inv;
    }
}

// ---------------- launch ----------------
extern "C" void kernel_launch(void* const* d_in, const int* in_sizes, int n_in,
                              void* d_out, int out_size) {
    const float* x = (const float*)d_in[0];
    const int* ei = (const int*)d_in[1];
    const int* src = ei;
    const int* dst = ei + EE;
    const float* Wl1 = (const float*)d_in[2];
    const float* bl1 = (const float*)d_in[3];
    const float* Wr1 = (const float*)d_in[4];
    const float* Wl2 = (const float*)d_in[5];
    const float* bl2 = (const float*)d_in[6];
    const float* Wr2 = (const float*)d_in[7];
    const float* W4  = (const float*)d_in[8];
    const float* b4  = (const float*)d_in[9];
    const float* W5  = (const float*)d_in[10];
    const float* b5  = (const float*)d_in[11];
    const float* wp1 = (const float*)d_in[12];
    const float* wp2 = (const float*)d_in[13];
    const float* wp4 = (const float*)d_in[14];
    const float* wp5 = (const float*)d_in[15];
    const float* Wa  = (const float*)d_in[16];
    const float* ba  = (const float*)d_in[17];
    const float* Wb  = (const float*)d_in[18];
    const float* bb  = (const float*)d_in[19];
    const float* Wc  = (const float*)d_in[20];
    const float* bc  = (const float*)d_in[21];
    float* out = (float*)d_out;

    // CSR build
    hist_kernel<<<EE / 256, 256>>>(dst, Wl2, Wr2, W4, W5);
    scanfused_kernel<<<128, 256>>>();
    scatter_kernel<<<EE / 256, 256>>>(src, dst);

    // stage 1: SAGE1 on all N nodes, pool 16384 -> 8192 (c2o current = B)
    conv1_kernel<<<NN / 8, 256>>>(x, Wl1, bl1, Wr1, wp1);
    selcompact_kernel<<<GB, 1024>>>(16384, 8192, 0, 1);
    copyro_kernel<<<(GB * 8192) / 8, 256>>>(8192, 0, 1, 1);

    // stage 2: SAGE2 on 65536 nodes (live-edge lists), pool 8192 -> 4096 (c2o -> A)
    sage_fused_kernel<<<65536 / 32, 256>>>(bl2, wp2);
    selcompact_kernel<<<GB, 1024>>>(8192, 4096, 1, 0);
    copyro_kernel<<<(GB * 4096) / 8, 256>>>(4096, 1, 0, 1);

    // stage 3: GCN on 32768 nodes, pool 4096 -> 2048 (c2o -> B)
    xw_kernel<<<32768 / 32, 256>>>(32768, 2);
    gcn_kernel<<<32768 / 8, 256>>>(32768, b4, wp4);
    selcompact_kernel<<<GB, 1024>>>(4096, 2048, 0, 0);
    copyro_kernel<<<(GB * 2048) / 8, 256>>>(2048, 2, 1, 1);

    // stage 4: GCN on 16384 nodes, pool 2048 -> 1024 (c2o -> A)
    xw_kernel<<<16384 / 32, 256>>>(16384, 3);
    gcn_kernel<<<16384 / 8, 256>>>(16384, b5, wp5);
    selcompact_kernel<<<GB, 1024>>>(2048, 1024, 1, 0);
    copyro_kernel<<<(GB * 1024) / 8, 256>>>(1024, 3, 0, 0);

    // final MLP + softmax
    mlp_kernel<<<1, 1024>>>(Wa, ba, Wb, bb, Wc, bc, out);
}

// round 17
// speedup vs baseline: 1.0970x; 1.0296x over previous
#include <cuda_runtime.h>

#define NN 131072
#define EE 2097152
#define GB 8
#define CWD 64
#define EMAX 64

// ---------------- static device scratch ----------------
__device__ __align__(16) int d_cnt[NN];
__device__ int d_rowptr[NN + 1];
__device__ int d_cursor[NN];
__device__ int d_csr_src[EE];
__device__ unsigned d_agg[128];          // lookback aggregates (flag in bit31)
__device__ float d_hA[NN * CWD];
__device__ float d_hB[NN * CWD];
__device__ float d_xw[NN * CWD];
__device__ float d_score[NN];
__device__ float d_dis[NN];
__device__ int d_c2oA[NN];
__device__ int d_c2oB[NN];
__device__ int d_o2c[NN];
__device__ int d_oldidx[NN];
__device__ int d_nedge[NN];              // live-edge count per current node
__device__ int d_elist[NN * EMAX];       // live relabeled neighbor indices
__device__ unsigned d_romax[4 * GB * CWD];
__device__ float d_rosum[4 * GB * CWD];
__device__ float d_WT[4][CWD * CWD];  // transposed Wl2, Wr2, W4, W5

__device__ __forceinline__ unsigned fkey(float f) {
    unsigned b = __float_as_uint(f);
    return (b & 0x80000000u) ? ~b : (b | 0x80000000u);
}
__device__ __forceinline__ float unfkey(unsigned u) {
    unsigned b = (u & 0x80000000u) ? (u & 0x7fffffffu) : ~u;
    return __uint_as_float(b);
}

__device__ __forceinline__ int wscan_incl(int v, int lane) {
    int incl = v;
    #pragma unroll
    for (int off = 1; off < 32; off <<= 1) {
        int n = __shfl_up_sync(0xffffffffu, incl, off);
        if (lane >= off) incl += n;
    }
    return incl;
}

// ---------------- hist (int4 x 4 edges/thread) + folded init work ----------------
__global__ void hist_kernel(const int* __restrict__ dst,
                            const float* __restrict__ Wl2, const float* __restrict__ Wr2,
                            const float* __restrict__ W4, const float* __restrict__ W5) {
    int e = blockIdx.x * blockDim.x + threadIdx.x;   // e in [0, EE/4)
    int4 d4 = ((const int4*)dst)[e];
    atomicAdd(&d_cnt[d4.x], 1);
    atomicAdd(&d_cnt[d4.y], 1);
    atomicAdd(&d_cnt[d4.z], 1);
    atomicAdd(&d_cnt[d4.w], 1);
    if (e < 4 * GB * CWD) { d_romax[e] = 0u; d_rosum[e] = 0.f; }
    if (e < 4 * 4096) {
        int slot = e >> 12;
        int j = e & 4095;
        const float* W = slot == 0 ? Wl2 : slot == 1 ? Wr2 : slot == 2 ? W4 : W5;
        int r = j >> 6, c = j & 63;
        d_WT[slot][c * 64 + r] = W[j];
    }
}

// ---------------- single-kernel scan (decoupled lookback, 128 blocks co-resident) ----------------
__global__ void __launch_bounds__(256, 4) scanfused_kernel() {
    __shared__ int s_warp[8];
    __shared__ int s_off;
    int t = threadIdx.x, b = blockIdx.x;
    int lane = t & 31, w = t >> 5;
    int i0 = b * 1024 + t * 4;
    int4 v = *(const int4*)&d_cnt[i0];
    int s = v.x + v.y + v.z + v.w;
    int incl = wscan_incl(s, lane);
    if (lane == 31) s_warp[w] = incl;
    __syncthreads();
    if (t == 0) {
        int acc = 0;
        #pragma unroll
        for (int ww = 0; ww < 8; ww++) { int tmp = s_warp[ww]; s_warp[ww] = acc; acc += tmp; }
        __threadfence();
        ((volatile unsigned*)d_agg)[b] = (unsigned)acc | 0x80000000u;   // publish aggregate
    } else if (w == 1) {
        int off = 0;
        for (int j = lane; j < b; j += 32) {
            unsigned a;
            do { a = ((volatile unsigned*)d_agg)[j]; } while (!(a >> 31));
            off += (int)(a & 0x7fffffffu);
        }
        for (int o = 16; o; o >>= 1) off += __shfl_xor_sync(0xffffffffu, off, o);
        if (lane == 0) s_off = off;
    }
    __syncthreads();
    int ex = s_off + s_warp[w] + incl - s;
    d_rowptr[i0] = ex;
    d_rowptr[i0 + 1] = ex + v.x;
    d_rowptr[i0 + 2] = ex + v.x + v.y;
    d_rowptr[i0 + 3] = ex + v.x + v.y + v.z;
    d_cursor[i0] = ex;
    d_cursor[i0 + 1] = ex + v.x;
    d_cursor[i0 + 2] = ex + v.x + v.y;
    d_cursor[i0 + 3] = ex + v.x + v.y + v.z;
    *(int4*)&d_cnt[i0] = make_int4(0, 0, 0, 0);   // re-zero for next call
    if (b == 127 && t == 0) d_rowptr[NN] = EE;
}

// ---------------- scatter (int4 x 4 edges/thread) ----------------
__global__ void scatter_kernel(const int* __restrict__ src, const int* __restrict__ dst) {
    int e = blockIdx.x * blockDim.x + threadIdx.x;   // e in [0, EE/4)
    int4 s4 = ((const int4*)src)[e];
    int4 d4 = ((const int4*)dst)[e];
    int p0 = atomicAdd(&d_cursor[d4.x], 1);
    int p1 = atomicAdd(&d_cursor[d4.y], 1);
    int p2 = atomicAdd(&d_cursor[d4.z], 1);
    int p3 = atomicAdd(&d_cursor[d4.w], 1);
    d_csr_src[p0] = s4.x;
    d_csr_src[p1] = s4.y;
    d_csr_src[p2] = s4.z;
    d_csr_src[p3] = s4.w;
    if (e < 128) d_agg[e] = 0;   // reset lookback flags for next call
}

// ---------------- conv1: SAGE (2 -> 64), 2 nodes per warp ----------------
__global__ void conv1_kernel(const float* __restrict__ x,
                             const float* __restrict__ Wl, const float* __restrict__ bl,
                             const float* __restrict__ Wr, const float* __restrict__ wp) {
    int warp = (blockIdx.x * blockDim.x + threadIdx.x) >> 5;
    int lane = threadIdx.x & 31;
    int half = lane >> 4;
    int hl = lane & 15;
    int n = warp * 2 + half;
    if (n >= NN) return;
    const float2* x2 = (const float2*)x;
    int row = d_rowptr[n], end = d_rowptr[n + 1];
    float a0 = 0.f, a1 = 0.f;
    for (int e = row + hl; e < end; e += 16) {
        float2 v = x2[d_csr_src[e]];
        a0 += v.x;
        a1 += v.y;
    }
    #pragma unroll
    for (int o = 8; o; o >>= 1) {
        a0 += __shfl_xor_sync(0xffffffffu, a0, o);
        a1 += __shfl_xor_sync(0xffffffffu, a1, o);
    }
    float deg = (float)(end - row);
    float inv = deg > 0.f ? 1.f / deg : 0.f;
    float m0 = a0 * inv, m1 = a1 * inv;
    float2 xv = x2[n];
    // each lane owns dims 4*hl .. 4*hl+3 of its node
    float4 wlA = *(const float4*)&Wl[8 * hl];
    float4 wlB = *(const float4*)&Wl[8 * hl + 4];
    float4 wrA = *(const float4*)&Wr[8 * hl];
    float4 wrB = *(const float4*)&Wr[8 * hl + 4];
    float4 bl4 = *(const float4*)&bl[4 * hl];
    float o0 = wlA.x * m0 + wlA.y * m1 + bl4.x + wrA.x * xv.x + wrA.y * xv.y;
    float o1 = wlA.z * m0 + wlA.w * m1 + bl4.y + wrA.z * xv.x + wrA.w * xv.y;
    float o2 = wlB.x * m0 + wlB.y * m1 + bl4.z + wrB.x * xv.x + wrB.y * xv.y;
    float o3 = wlB.z * m0 + wlB.w * m1 + bl4.w + wrB.z * xv.x + wrB.w * xv.y;
    o0 = fmaxf(o0, 0.f); o1 = fmaxf(o1, 0.f);
    o2 = fmaxf(o2, 0.f); o3 = fmaxf(o3, 0.f);
    *(float4*)&d_hA[n * 64 + 4 * hl] = make_float4(o0, o1, o2, o3);
    float4 wp4 = *(const float4*)&wp[4 * hl];
    float sd = o0 * wp4.x + o1 * wp4.y + o2 * wp4.z + o3 * wp4.w;
    float nw = wp4.x * wp4.x + wp4.y * wp4.y + wp4.z * wp4.z + wp4.w * wp4.w;
    #pragma unroll
    for (int o = 8; o; o >>= 1) {
        sd += __shfl_xor_sync(0xffffffffu, sd, o);
        nw += __shfl_xor_sync(0xffffffffu, nw, o);
    }
    if (hl == 0) d_score[n] = tanhf(sd * rsqrtf(nw));
}

// ---------------- fused radix select + compact (one block per graph, parallel bin scan) ----------------
__global__ void __launch_bounds__(1024, 1) selcompact_kernel(int m, int k, int flip, int identity) {
    __shared__ unsigned hist[256];
    __shared__ int s_wsum[8];
    __shared__ unsigned s_pref;
    __shared__ int s_rem;
    __shared__ int s_ctr;
    __shared__ int s_eq;
    int b = blockIdx.x, t = threadIdx.x;
    int lane = t & 31;
    int base = b * m;
    if (t == 0) { s_pref = 0u; s_rem = k; }
    __syncthreads();
    for (int p = 3; p >= 0; p--) {
        if (t < 256) hist[t] = 0;
        __syncthreads();
        unsigned pref = s_pref;
        int rem_in = s_rem;
        int hs = (p + 1) * 8;
        for (int i = t; i < m; i += 1024) {
            unsigned u = fkey(d_score[base + i]);
            bool cand = (p == 3) || ((u >> hs) == (pref >> hs));
            if (cand) atomicAdd(&hist[(u >> (p * 8)) & 255], 1u);
        }
        __syncthreads();
        unsigned x = 0, incl = 0;
        if (t < 256) {
            int rt = 255 - t;
            x = hist[rt];
            incl = (unsigned)wscan_incl((int)x, lane);
            if (lane == 31) s_wsum[t >> 5] = (int)incl;
        }
        __syncthreads();
        if (t == 0) {
            int acc = 0;
            #pragma unroll
            for (int ww = 0; ww < 8; ww++) { int tmp = s_wsum[ww]; s_wsum[ww] = acc; acc += tmp; }
        }
        __syncthreads();
        if (t < 256) {
            int rt = 255 - t;
            unsigned g = (unsigned)s_wsum[t >> 5] + incl;
            unsigned above = g - x;
            if ((unsigned)rem_in > above && (unsigned)rem_in <= g) {
                s_pref = pref | ((unsigned)rt << (p * 8));
                s_rem = rem_in - (int)above;
            }
        }
        __syncthreads();
    }
    if (t == 0) { s_ctr = 0; s_eq = 0; }
    __syncthreads();
    unsigned th = s_pref;
    int quota = s_rem;
    const int* oldm = flip ? d_c2oB : d_c2oA;
    int* newm = flip ? d_c2oA : d_c2oB;
    for (int i = t; i < m; i += 1024) {
        int c = base + i;
        unsigned u = fkey(d_score[c]);
        bool keep = u > th;
        if (!keep && u == th) keep = (atomicAdd(&s_eq, 1) < quota);
        int orig = identity ? c : oldm[c];
        unsigned keepers = __ballot_sync(0xffffffffu, keep);
        int cnt = __popc(keepers);
        int base_slot = 0;
        if (lane == 0 && cnt > 0) base_slot = atomicAdd(&s_ctr, cnt);
        base_slot = __shfl_sync(0xffffffffu, base_slot, 0);
        if (keep) {
            int slot = base_slot + __popc(keepers & ((1u << lane) - 1u));
            int nc = b * k + slot;
            newm[nc] = orig;
            d_o2c[orig] = nc;
            d_oldidx[nc] = c;
        } else {
            d_o2c[orig] = -1;
        }
    }
}

// ---------------- pool copy + readout partials + live-edge list build ----------------
__global__ void __launch_bounds__(256) copyro_kernel(int k, int stage, int sel, int build) {
    __shared__ float sv[8][64];
    int gw = (blockIdx.x * blockDim.x + threadIdx.x) >> 5;
    int w = (threadIdx.x >> 5);
    int lane = threadIdx.x & 31;
    int oldc = d_oldidx[gw];
    float v = d_score[oldc];
    float2 h = *(const float2*)&d_hA[oldc * 64 + 2 * lane];
    float v0 = h.x * v, v1 = h.y * v;
    *(float2*)&d_hB[gw * 64 + 2 * lane] = make_float2(v0, v1);
    sv[w][2 * lane] = v0;
    sv[w][2 * lane + 1] = v1;

    if (build) {
        const int* c2o = sel ? d_c2oB : d_c2oA;
        int o = c2o[gw];
        int row = d_rowptr[o], end = d_rowptr[o + 1];
        int cnt = 0;
        for (int base = row; base < end; base += 32) {
            int e = base + lane;
            int sc = (e < end) ? d_o2c[d_csr_src[e]] : -1;
            unsigned liveb = __ballot_sync(0xffffffffu, sc >= 0);
            int pos = cnt + __popc(liveb & ((1u << lane) - 1u));
            if (sc >= 0 && pos < EMAX) d_elist[gw * EMAX + pos] = sc;
            cnt += __popc(liveb);
        }
        if (lane == 0) {
            d_nedge[gw] = min(cnt, EMAX);
            d_dis[gw] = rsqrtf(1.f + (float)cnt);
        }
    }

    __syncthreads();
    int t = threadIdx.x;
    if (t < 64) {
        float mx = sv[0][t], sm = 0.f;
        #pragma unroll
        for (int ww = 0; ww < 8; ww++) {
            float f = sv[ww][t];
            mx = fmaxf(mx, f);
            sm += f;
        }
        int b = (blockIdx.x * 8) / k;
        int off = stage * GB * 64 + b * 64 + t;
        atomicMax(&d_romax[off], fkey(mx));
        atomicAdd(&d_rosum[off], sm);
    }
}

// ---------------- SAGE2 fused: live-edge MLP-4 agg + tiled transform ----------------
__global__ void __launch_bounds__(256) sage_fused_kernel(const float* __restrict__ bl,
                                                         const float* __restrict__ wp) {
    __shared__ float sWl[4096];
    __shared__ float sWr[4096];
    __shared__ float sm_m[32][64];
    int t = threadIdx.x;
    for (int i = t; i < 4096; i += 256) {
        sWl[i] = d_WT[0][i];
        sWr[i] = d_WT[1][i];
    }
    int lane = t & 31;
    int w = t >> 5;
    int nblock = blockIdx.x * 32;

    for (int q = 0; q < 4; q++) {
        int n = nblock + w * 4 + q;
        int cnt = d_nedge[n];
        float a0x = 0.f, a0y = 0.f, a1x = 0.f, a1y = 0.f;
        float a2x = 0.f, a2y = 0.f, a3x = 0.f, a3y = 0.f;
        for (int base = 0; base < cnt; base += 32) {
            int e = base + lane;
            int sc = (e < cnt) ? d_elist[n * EMAX + e] : -1;
            int nb = min(32, cnt - base);
            for (int j = 0; j < nb; j += 4) {
                int s0 = __shfl_sync(0xffffffffu, sc, j);
                int s1 = __shfl_sync(0xffffffffu, sc, j + 1);
                int s2 = __shfl_sync(0xffffffffu, sc, j + 2);
                int s3 = __shfl_sync(0xffffffffu, sc, j + 3);
                float2 v0 = (s0 >= 0) ? *(const float2*)&d_hB[s0 * 64 + 2 * lane] : make_float2(0.f, 0.f);
                float2 v1 = (s1 >= 0) ? *(const float2*)&d_hB[s1 * 64 + 2 * lane] : make_float2(0.f, 0.f);
                float2 v2 = (s2 >= 0) ? *(const float2*)&d_hB[s2 * 64 + 2 * lane] : make_float2(0.f, 0.f);
                float2 v3 = (s3 >= 0) ? *(const float2*)&d_hB[s3 * 64 + 2 * lane] : make_float2(0.f, 0.f);
                a0x += v0.x; a0y += v0.y;
                a1x += v1.x; a1y += v1.y;
                a2x += v2.x; a2y += v2.y;
                a3x += v3.x; a3y += v3.y;
            }
        }
        float invc = cnt ? 1.f / (float)cnt : 0.f;
        sm_m[w * 4 + q][2 * lane] = (a0x + a1x + a2x + a3x) * invc;
        sm_m[w * 4 + q][2 * lane + 1] = (a0y + a1y + a2y + a3y) * invc;
    }
    __syncthreads();

    int n0 = nblock + w * 4;
    float mA[4], mB[4], hA[4], hB[4], o0[4], o1[4];
    #pragma unroll
    for (int q = 0; q < 4; q++) {
        int n = n0 + q;
        mA[q] = sm_m[w * 4 + q][lane];
        mB[q] = sm_m[w * 4 + q][lane + 32];
        hA[q] = d_hB[n * 64 + lane];
        hB[q] = d_hB[n * 64 + lane + 32];
        o0[q] = 0.f; o1[q] = 0.f;
    }
    #pragma unroll 4
    for (int j = 0; j < 32; j++) {
        float wl0 = sWl[j * 64 + lane], wl1 = sWl[j * 64 + lane + 32];
        float wr0 = sWr[j * 64 + lane], wr1 = sWr[j * 64 + lane + 32];
        #pragma unroll
        for (int q = 0; q < 4; q++) {
            float mj = __shfl_sync(0xffffffffu, mA[q], j);
            float hj = __shfl_sync(0xffffffffu, hA[q], j);
            o0[q] += wl0 * mj + wr0 * hj;
            o1[q] += wl1 * mj + wr1 * hj;
        }
    }
    #pragma unroll 4
    for (int j = 32; j < 64; j++) {
        float wl0 = sWl[j * 64 + lane], wl1 = sWl[j * 64 + lane + 32];
        float wr0 = sWr[j * 64 + lane], wr1 = sWr[j * 64 + lane + 32];
        #pragma unroll
        for (int q = 0; q < 4; q++) {
            float mj = __shfl_sync(0xffffffffu, mB[q], j - 32);
            float hj = __shfl_sync(0xffffffffu, hB[q], j - 32);
            o0[q] += wl0 * mj + wr0 * hj;
            o1[q] += wl1 * mj + wr1 * hj;
        }
    }
    float b0 = bl[lane], b1 = bl[lane + 32];
    float w0 = wp[lane], w1 = wp[lane + 32];
    float nw = w0 * w0 + w1 * w1;
    for (int o = 16; o; o >>= 1) nw += __shfl_xor_sync(0xffffffffu, nw, o);
    float rn = rsqrtf(nw);
    #pragma unroll
    for (int q = 0; q < 4; q++) {
        int n = n0 + q;
        float r0 = fmaxf(o0[q] + b0, 0.f);
        float r1 = fmaxf(o1[q] + b1, 0.f);
        d_hA[n * 64 + lane] = r0;
        d_hA[n * 64 + lane + 32] = r1;
        float sd = r0 * w0 + r1 * w1;
        for (int o = 16; o; o >>= 1) sd += __shfl_xor_sync(0xffffffffu, sd, o);
        if (lane == 0) d_score[n] = tanhf(sd * rn);
    }
}

// ---------------- GCN xw transform (tiled, pure) ----------------
__global__ void __launch_bounds__(256) xw_kernel(int M, int slot) {
    __shared__ float sW[4096];
    int t = threadIdx.x;
    for (int i = t; i < 4096; i += 256) sW[i] = d_WT[slot][i];
    __syncthreads();
    int lane = t & 31;
    int gw = (blockIdx.x * 8) + (t >> 5);
    int n0 = gw * 4;
    float hA[4], hB[4], o0[4], o1[4];
    #pragma unroll
    for (int q = 0; q < 4; q++) {
        int n = n0 + q;
        hA[q] = d_hB[n * 64 + lane];
        hB[q] = d_hB[n * 64 + lane + 32];
        o0[q] = 0.f; o1[q] = 0.f;
    }
    #pragma unroll 4
    for (int j = 0; j < 32; j++) {
        float w0 = sW[j * 64 + lane], w1 = sW[j * 64 + lane + 32];
        #pragma unroll
        for (int q = 0; q < 4; q++) {
            float hj = __shfl_sync(0xffffffffu, hA[q], j);
            o0[q] += w0 * hj;
            o1[q] += w1 * hj;
        }
    }
    #pragma unroll 4
    for (int j = 32; j < 64; j++) {
        float w0 = sW[j * 64 + lane], w1 = sW[j * 64 + lane + 32];
        #pragma unroll
        for (int q = 0; q < 4; q++) {
            float hj = __shfl_sync(0xffffffffu, hB[q], j - 32);
            o0[q] += w0 * hj;
            o1[q] += w1 * hj;
        }
    }
    #pragma unroll
    for (int q = 0; q < 4; q++) {
        int n = n0 + q;
        d_xw[n * 64 + lane] = o0[q];
        d_xw[n * 64 + lane + 32] = o1[q];
    }
}

// ---------------- GCN aggregation + epilogue (live-edge MLP-4) ----------------
__global__ void __launch_bounds__(256) gcn_kernel(int M, const float* __restrict__ bias,
                                                  const float* __restrict__ wp) {
    int gw = (blockIdx.x * blockDim.x + threadIdx.x) >> 5;
    if (gw >= M) return;
    int lane = threadIdx.x & 31;
    float dd = d_dis[gw];
    int cnt = d_nedge[gw];
    float a0x = 0.f, a0y = 0.f, a1x = 0.f, a1y = 0.f;
    float a2x = 0.f, a2y = 0.f, a3x = 0.f, a3y = 0.f;
    for (int base = 0; base < cnt; base += 32) {
        int e = base + lane;
        int sc = (e < cnt) ? d_elist[gw * EMAX + e] : -1;
        int nb = min(32, cnt - base);
        for (int j = 0; j < nb; j += 4) {
            int s0 = __shfl_sync(0xffffffffu, sc, j);
            int s1 = __shfl_sync(0xffffffffu, sc, j + 1);
            int s2 = __shfl_sync(0xffffffffu, sc, j + 2);
            int s3 = __shfl_sync(0xffffffffu, sc, j + 3);
            float d0 = (s0 >= 0) ? d_dis[s0] : 0.f;
            float d1 = (s1 >= 0) ? d_dis[s1] : 0.f;
            float d2 = (s2 >= 0) ? d_dis[s2] : 0.f;
            float d3 = (s3 >= 0) ? d_dis[s3] : 0.f;
            float2 v0 = (s0 >= 0) ? *(const float2*)&d_xw[s0 * 64 + 2 * lane] : make_float2(0.f, 0.f);
            float2 v1 = (s1 >= 0) ? *(const float2*)&d_xw[s1 * 64 + 2 * lane] : make_float2(0.f, 0.f);
            float2 v2 = (s2 >= 0) ? *(const float2*)&d_xw[s2 * 64 + 2 * lane] : make_float2(0.f, 0.f);
            float2 v3 = (s3 >= 0) ? *(const float2*)&d_xw[s3 * 64 + 2 * lane] : make_float2(0.f, 0.f);
            a0x += v0.x * d0; a0y += v0.y * d0;
            a1x += v1.x * d1; a1y += v1.y * d1;
            a2x += v2.x * d2; a2y += v2.y * d2;
            a3x += v3.x * d3; a3y += v3.y * d3;
        }
    }
    float ax = (a0x + a1x + a2x + a3x) * dd;
    float ay = (a0y + a1y + a2y + a3y) * dd;
    float2 self = *(const float2*)&d_xw[gw * 64 + 2 * lane];
    float o0 = ax + self.x * dd * dd + bias[2 * lane];
    float o1 = ay + self.y * dd * dd + bias[2 * lane + 1];
    o0 = fmaxf(o0, 0.f); o1 = fmaxf(o1, 0.f);
    *(float2*)&d_hA[gw * 64 + 2 * lane] = make_float2(o0, o1);
    float w0 = wp[2 * lane], w1 = wp[2 * lane + 1];
    float sd = o0 * w0 + o1 * w1, nw = w0 * w0 + w1 * w1;
    for (int s = 16; s; s >>= 1) {
        sd += __shfl_xor_sync(0xffffffffu, sd, s);
        nw += __shfl_xor_sync(0xffffffffu, nw, s);
    }
    if (lane == 0) d_score[gw] = tanhf(sd * rsqrtf(nw));
}

// ---------------- final MLP + softmax ----------------
__global__ void __launch_bounds__(1024, 1) mlp_kernel(const float* __restrict__ Wa, const float* __restrict__ ba,
                           const float* __restrict__ Wb, const float* __restrict__ bb,
                           const float* __restrict__ Wc, const float* __restrict__ bc,
                           float* __restrict__ out) {
    __shared__ float zs[1024];
    __shared__ float za[1024];
    __shared__ float zb[512];
    __shared__ float zc[2048];
    int t = threadIdx.x;
    {
        int b = t >> 7, d = t & 127;
        const float invk[4] = {1.f / 8192.f, 1.f / 4096.f, 1.f / 2048.f, 1.f / 1024.f};
        float acc = 0.f;
        if (d < 64) {
            #pragma unroll
            for (int st = 0; st < 4; st++)
                acc += unfkey(d_romax[st * GB * 64 + b * 64 + d]);
        } else {
            #pragma unroll
            for (int st = 0; st < 4; st++)
                acc += d_rosum[st * GB * 64 + b * 64 + (d - 64)] * invk[st];
        }
        zs[t] = acc;
    }
    __syncthreads();
    {
        int b = t >> 7, o = t & 127;
        float a = ba[o];
        const float* w = Wa + o * 128;
        const float* z = zs + b * 128;
        for (int j = 0; j < 128; j++) a += w[j] * z[j];
        za[t] = fmaxf(a, 0.f);
    }
    __syncthreads();
    if (t < 512) {
        int b = t >> 6, o = t & 63;
        float a = bb[o];
        for (int j = 0; j < 128; j++) a += Wb[o * 128 + j] * za[b * 128 + j];
        zb[t] = fmaxf(a, 0.f);
    }
    __syncthreads();
    for (int q = t; q < 2048; q += 1024) {
        int b = q >> 8, o = q & 255;
        float a = bc[o];
        for (int j = 0; j < 64; j++) a += Wc[o * 64 + j] * zb[b * 64 + j];
        zc[q] = a;
    }
    __syncthreads();
    int w = t >> 5, lane = t & 31;
    if (w < 8) {
        float mx = -3.4e38f;
        for (int i = lane; i < 256; i += 32) mx = fmaxf(mx, zc[w * 256 + i]);
        for (int o = 16; o; o >>= 1) mx = fmaxf(mx, __shfl_xor_sync(0xffffffffu, mx, o));
        float s = 0.f;
        for (int i = lane; i < 256; i += 32) {
            float e = expf(zc[w * 256 + i] - mx);
            zc[w * 256 + i] = e;
            s += e;
        }
        for (int o = 16; o; o >>= 1) s += __shfl_xor_sync(0xffffffffu, s, o);
        float inv = 1.f / s;
        for (int i = lane; i < 256; i += 32) out[w * 256 + i] = zc[w * 256 + i] * inv;
    }
}

// ---------------- launch ----------------
extern "C" void kernel_launch(void* const* d_in, const int* in_sizes, int n_in,
                              void* d_out, int out_size) {
    const float* x = (const float*)d_in[0];
    const int* ei = (const int*)d_in[1];
    const int* src = ei;
    const int* dst = ei + EE;
    const float* Wl1 = (const float*)d_in[2];
    const float* bl1 = (const float*)d_in[3];
    const float* Wr1 = (const float*)d_in[4];
    const float* Wl2 = (const float*)d_in[5];
    const float* bl2 = (const float*)d_in[6];
    const float* Wr2 = (const float*)d_in[7];
    const float* W4  = (const float*)d_in[8];
    const float* b4  = (const float*)d_in[9];
    const float* W5  = (const float*)d_in[10];
    const float* b5  = (const float*)d_in[11];
    const float* wp1 = (const float*)d_in[12];
    const float* wp2 = (const float*)d_in[13];
    const float* wp4 = (const float*)d_in[14];
    const float* wp5 = (const float*)d_in[15];
    const float* Wa  = (const float*)d_in[16];
    const float* ba  = (const float*)d_in[17];
    const float* Wb  = (const float*)d_in[18];
    const float* bb  = (const float*)d_in[19];
    const float* Wc  = (const float*)d_in[20];
    const float* bc  = (const float*)d_in[21];
    float* out = (float*)d_out;

    // CSR build (vectorized edge streams)
    hist_kernel<<<EE / 4 / 256, 256>>>(dst, Wl2, Wr2, W4, W5);
    scanfused_kernel<<<128, 256>>>();
    scatter_kernel<<<EE / 4 / 256, 256>>>(src, dst);

    // stage 1: SAGE1 on all N nodes (2 nodes/warp), pool 16384 -> 8192 (c2o current = B)
    conv1_kernel<<<NN / 16, 256>>>(x, Wl1, bl1, Wr1, wp1);
    selcompact_kernel<<<GB, 1024>>>(16384, 8192, 0, 1);
    copyro_kernel<<<(GB * 8192) / 8, 256>>>(8192, 0, 1, 1);

    // stage 2: SAGE2 on 65536 nodes (live-edge lists), pool 8192 -> 4096 (c2o -> A)
    sage_fused_kernel<<<65536 / 32, 256>>>(bl2, wp2);
    selcompact_kernel<<<GB, 1024>>>(8192, 4096, 1, 0);
    copyro_kernel<<<(GB * 4096) / 8, 256>>>(4096, 1, 0, 1);

    // stage 3: GCN on 32768 nodes, pool 4096 -> 2048 (c2o -> B)
    xw_kernel<<<32768 / 32, 256>>>(32768, 2);
    gcn_kernel<<<32768 / 8, 256>>>(32768, b4, wp4);
    selcompact_kernel<<<GB, 1024>>>(4096, 2048, 0, 0);
    copyro_kernel<<<(GB * 2048) / 8, 256>>>(2048, 2, 1, 1);

    // stage 4: GCN on 16384 nodes, pool 2048 -> 1024 (c2o -> A)
    xw_kernel<<<16384 / 32, 256>>>(16384, 3);
    gcn_kernel<<<16384 / 8, 256>>>(16384, b5, wp5);
    selcompact_kernel<<<GB, 1024>>>(2048, 1024, 1, 0);
    copyro_kernel<<<(GB * 1024) / 8, 256>>>(1024, 3, 0, 0);

    // final MLP + softmax
    mlp_kernel<<<1, 1024>>>(Wa, ba, Wb, bb, Wc, bc, out);
}